// round 16
// baseline (speedup 1.0000x reference)
#include <cuda_runtime.h>

#define N_NODES 50000
#define E_EDGES 800000
#define IN_DIM  128
#define OUT_DIM 64

#define SCAN_BLK 256
#define N_SBLK ((N_NODES + SCAN_BLK - 1) / SCAN_BLK)   // 196
#define K1_BLOCKS 1024
#define KC_BLOCKS 32          // 32*256 = 8192 = 128*64 outputs
#define CNT_BLOCKS 512

// ---------------- scratch (device globals; allocation-free) ----------------
__device__ __align__(16) float g_z[N_NODES * OUT_DIM];   // 12.8 MB (L2-resident)
__device__ __align__(16) float g_sl[N_NODES * OUT_DIM];  // self-loop term
__device__ __align__(16) float g_cw[IN_DIM * OUT_DIM];   // C = W^T @ LW  [128][64]
__device__ float g_s1[N_NODES];
__device__ float g_s2[N_NODES];
__device__ int   g_deg[N_NODES];        // zero at call entry (BSS / re-zeroed by scanC)
__device__ int   g_off[N_NODES + 1];    // CSR offsets by dst
__device__ int   g_cur[N_NODES];        // running fill cursor
__device__ int   g_bsum[N_SBLK];        // per-block degree sums
__device__ __align__(8) int2 g_cedge[E_EDGES];  // packed {src, exp_bits} per CSR slot

// ============================================================================
// kCcount: blocks [0, KC_BLOCKS): C[k][j] = sum_o W[o][k]*LW[o][j], one
// output per thread with 4 independent accumulators (breaks FMA chain).
// Blocks [KC_BLOCKS, ...): dst degree histogram (latency work, overlapped).
// ============================================================================
__global__ void __launch_bounds__(256) kCcount(
    const float* __restrict__ W,    // [64][128]
    const float* __restrict__ LW,   // [64][64]
    const int*   __restrict__ dst)
{
    const int tid = threadIdx.x;

    if (blockIdx.x >= KC_BLOCKS) {
        // ---------------- degree count (g_deg starts zeroed) ----------------
        const int cbid = blockIdx.x - KC_BLOCKS;
        const int t4 = cbid * 256 + tid;                 // int4 index
        const int n4 = E_EDGES / 4;
        const int stride = CNT_BLOCKS * 256;
        for (int i = t4; i < n4; i += stride) {
            const int4 d = ((const int4*)dst)[i];
            atomicAdd(&g_deg[d.x], 1);
            atomicAdd(&g_deg[d.y], 1);
            atomicAdd(&g_deg[d.z], 1);
            atomicAdd(&g_deg[d.w], 1);
        }
        return;
    }

    const int idx = blockIdx.x * 256 + tid;   // 0..8191
    const int k = idx >> 6;                   // 0..127
    const int j = idx & 63;                   // 0..63
    float s0 = 0.f, s1 = 0.f, s2 = 0.f, s3 = 0.f;
    #pragma unroll
    for (int o = 0; o < OUT_DIM; o += 4) {
        s0 += W[(o + 0) * IN_DIM + k] * LW[(o + 0) * OUT_DIM + j];
        s1 += W[(o + 1) * IN_DIM + k] * LW[(o + 1) * OUT_DIM + j];
        s2 += W[(o + 2) * IN_DIM + k] * LW[(o + 2) * OUT_DIM + j];
        s3 += W[(o + 3) * IN_DIM + k] * LW[(o + 3) * OUT_DIM + j];
    }
    g_cw[idx] = (s0 + s1) + (s2 + s3);
}

// ============================================================================
// k_gemm (exact R14 GEMM branch): z = h@W^T, sl = h@C, s1/s2 reductions.
// ============================================================================
__global__ void __launch_bounds__(128) k_gemm(
    const float* __restrict__ h,
    const float* __restrict__ W,     // [64][128] row-major
    const float* __restrict__ attn)  // [192] = w1 | w2 | w3
{
    __shared__ __align__(16) float Wts[IN_DIM * 66];      // transposed, padded
    __shared__ __align__(16) float hw[4][IN_DIM][4];      // [warp][k][node-slot]

    const int tid = threadIdx.x;

    for (int i = tid; i < OUT_DIM * IN_DIM; i += blockDim.x) {
        int j = i >> 7;
        int k = i & 127;
        Wts[k * 66 + j] = W[i];
    }
    __syncthreads();

    const int w = tid >> 5;
    const int l = tid & 31;

    const float2 w1 = ((const float2*)attn)[l];
    const float2 w2 = ((const float2*)(attn + OUT_DIM))[l];

    const int ntasks_stride = K1_BLOCKS * 4;
    for (int task = blockIdx.x * 4 + w; task < N_NODES / 4; task += ntasks_stride) {
        const int node0 = task * 4;

        #pragma unroll
        for (int m = 0; m < 4; m++) {
            const float* hp = h + (size_t)(node0 + m) * IN_DIM;
            #pragma unroll
            for (int t = 0; t < 4; t++)
                hw[w][t * 32 + l][m] = hp[t * 32 + l];
        }
        __syncwarp();

        float a0x = 0.f, a0y = 0.f, a0z = 0.f, a0w = 0.f;   // z, out dim 2l
        float a1x = 0.f, a1y = 0.f, a1z = 0.f, a1w = 0.f;   // z, out dim 2l+1
        float b0x = 0.f, b0y = 0.f, b0z = 0.f, b0w = 0.f;   // sl, out dim 2l
        float b1x = 0.f, b1y = 0.f, b1z = 0.f, b1w = 0.f;   // sl, out dim 2l+1
        #pragma unroll 16
        for (int k = 0; k < IN_DIM; k++) {
            const float4 hq = *(const float4*)&hw[w][k][0];
            const float2 wv = *(const float2*)&Wts[k * 66 + 2 * l];
            const float2 cv = __ldg((const float2*)&g_cw[k * OUT_DIM + 2 * l]);
            a0x += wv.x * hq.x; a0y += wv.x * hq.y; a0z += wv.x * hq.z; a0w += wv.x * hq.w;
            a1x += wv.y * hq.x; a1y += wv.y * hq.y; a1z += wv.y * hq.z; a1w += wv.y * hq.w;
            b0x += cv.x * hq.x; b0y += cv.x * hq.y; b0z += cv.x * hq.z; b0w += cv.x * hq.w;
            b1x += cv.y * hq.x; b1y += cv.y * hq.y; b1z += cv.y * hq.z; b1w += cv.y * hq.w;
        }
        __syncwarp();

        const float acc0[4] = {a0x, a0y, a0z, a0w};
        const float acc1[4] = {a1x, a1y, a1z, a1w};
        const float sl0[4]  = {b0x, b0y, b0z, b0w};
        const float sl1[4]  = {b1x, b1y, b1z, b1w};
        #pragma unroll
        for (int m = 0; m < 4; m++) {
            const int node = node0 + m;
            const float zx = acc0[m], zy = acc1[m];
            *(float2*)&g_z[(size_t)node * OUT_DIM + 2 * l]  = make_float2(zx, zy);
            *(float2*)&g_sl[(size_t)node * OUT_DIM + 2 * l] = make_float2(sl0[m], sl1[m]);
            float v1 = zx * w1.x + zy * w1.y;
            float v2 = zx * w2.x + zy * w2.y;
            #pragma unroll
            for (int off = 16; off; off >>= 1) {
                v1 += __shfl_xor_sync(0xffffffffu, v1, off);
                v2 += __shfl_xor_sync(0xffffffffu, v2, off);
            }
            if (l == 0) {
                g_s1[node] = v1;
                g_s2[node] = v2;
            }
        }
    }
}

// ============================================================================
// scanA: per-block degree sums (exact R14)
// ============================================================================
__global__ void __launch_bounds__(SCAN_BLK) k_scanA()
{
    __shared__ int red[SCAN_BLK / 32];
    const int gid = blockIdx.x * SCAN_BLK + threadIdx.x;
    int v = (gid < N_NODES) ? g_deg[gid] : 0;
    #pragma unroll
    for (int off = 16; off; off >>= 1) v += __shfl_xor_sync(0xffffffffu, v, off);
    if ((threadIdx.x & 31) == 0) red[threadIdx.x >> 5] = v;
    __syncthreads();
    if (threadIdx.x == 0) {
        int s = 0;
        #pragma unroll
        for (int i = 0; i < SCAN_BLK / 32; i++) s += red[i];
        g_bsum[blockIdx.x] = s;
    }
}

// ============================================================================
// scanC: block-prefix + local exclusive scan + write off/cur + re-zero deg
// (exact R14)
// ============================================================================
__global__ void __launch_bounds__(SCAN_BLK) k_scanC()
{
    __shared__ int s[SCAN_BLK];
    __shared__ int red[SCAN_BLK / 32];
    __shared__ int s_pre;

    const int t = threadIdx.x;
    const int bid = blockIdx.x;
    const int gid = bid * SCAN_BLK + t;

    int mine = (t < bid) ? g_bsum[t] : 0;     // N_SBLK <= SCAN_BLK
    #pragma unroll
    for (int off = 16; off; off >>= 1) mine += __shfl_xor_sync(0xffffffffu, mine, off);
    if ((t & 31) == 0) red[t >> 5] = mine;
    __syncthreads();
    if (t == 0) {
        int p = 0;
        #pragma unroll
        for (int i = 0; i < SCAN_BLK / 32; i++) p += red[i];
        s_pre = p;
    }

    int v = (gid < N_NODES) ? g_deg[gid] : 0;
    s[t] = v;
    __syncthreads();
    #pragma unroll
    for (int off = 1; off < SCAN_BLK; off <<= 1) {
        int u = (t >= off) ? s[t - off] : 0;
        __syncthreads();
        s[t] += u;
        __syncthreads();
    }

    const int pre = s_pre;
    if (gid < N_NODES) {
        const int o = pre + s[t] - v;   // exclusive
        g_off[gid] = o;
        g_cur[gid] = o;
        g_deg[gid] = 0;                 // ready for next call
        if (gid == N_NODES - 1) g_off[N_NODES] = pre + s[t];
    }
}

// ============================================================================
// K2 (exact R14): logits -> exp -> direct CSR scatter. Half-warp per edge,
// 4 edges in flight. Streaming loads keep g_z resident in L2.
// ============================================================================
__global__ void __launch_bounds__(256) k2_scatter(
    const float* __restrict__ rh,
    const float* __restrict__ attn,
    const int* __restrict__ src,
    const int* __restrict__ dst)
{
    const int tid = blockIdx.x * blockDim.x + threadIdx.x;
    const int hw_id = tid >> 4;
    const int l = tid & 15;
    const int nhw = (gridDim.x * blockDim.x) >> 4;

    const float4 w3 = ((const float4*)(attn + 2 * OUT_DIM))[l];

    for (int e0 = hw_id * 4; e0 < E_EDGES; e0 += nhw * 4) {
        const float4 r0 = __ldcs((const float4*)(rh + (size_t)(e0 + 0) * OUT_DIM) + l);
        const float4 r1 = __ldcs((const float4*)(rh + (size_t)(e0 + 1) * OUT_DIM) + l);
        const float4 r2 = __ldcs((const float4*)(rh + (size_t)(e0 + 2) * OUT_DIM) + l);
        const float4 r3 = __ldcs((const float4*)(rh + (size_t)(e0 + 3) * OUT_DIM) + l);

        float p0 = r0.x * w3.x + r0.y * w3.y + r0.z * w3.z + r0.w * w3.w;
        float p1 = r1.x * w3.x + r1.y * w3.y + r1.z * w3.z + r1.w * w3.w;
        float p2 = r2.x * w3.x + r2.y * w3.y + r2.z * w3.z + r2.w * w3.w;
        float p3 = r3.x * w3.x + r3.y * w3.y + r3.z * w3.z + r3.w * w3.w;
        #pragma unroll
        for (int off = 8; off; off >>= 1) {
            p0 += __shfl_xor_sync(0xffffffffu, p0, off, 16);
            p1 += __shfl_xor_sync(0xffffffffu, p1, off, 16);
            p2 += __shfl_xor_sync(0xffffffffu, p2, off, 16);
            p3 += __shfl_xor_sync(0xffffffffu, p3, off, 16);
        }
        if (l < 4) {
            const int e = e0 + l;
            const float p = (l == 0) ? p0 : (l == 1) ? p1 : (l == 2) ? p2 : p3;
            const int s = src[e];
            const int d = dst[e];
            const float a = g_s1[s] + g_s2[d] + p;
            const float ev = (a > 0.f) ? a : 0.01f * a;   // leaky relu
            const float ex = __expf(ev);                  // no max-sub: |ev| small
            const int pos = atomicAdd(&g_cur[d], 1);
            g_cedge[pos] = make_int2(s, __float_as_int(ex));
        }
    }
}

// ============================================================================
// K_agg (exact R14): warp per node; halves process even/odd edges; lane owns
// 4 dims (float4); ~4 warp-instr/edge; cross-half combine via shfl_xor(16).
// ============================================================================
__global__ void __launch_bounds__(256) k_agg(float* __restrict__ out)
{
    const int node = (blockIdx.x * blockDim.x + threadIdx.x) >> 5;
    const int l = threadIdx.x & 31;
    const int half = l >> 4;     // 0 or 1
    const int lh = l & 15;       // lane within half
    if (node >= N_NODES) return;

    const int beg = g_off[node];
    const int end = g_off[node + 1];

    if (beg == end) {
        if (half == 0)
            *(float4*)&out[(size_t)node * OUT_DIM + 4 * lh] = make_float4(0.f, 0.f, 0.f, 0.f);
        return;
    }

    const float4 pre = *(const float4*)&g_sl[(size_t)node * OUT_DIM + 4 * lh];

    float4 acc = make_float4(0.f, 0.f, 0.f, 0.f);
    float denom = 0.f;

    for (int base = beg; base < end; base += 32) {
        const int idx = base + l;
        int2 ce = make_int2(0, 0);                 // weight bits 0 -> exp=0.0f
        if (idx < end) ce = g_cedge[idx];          // ONE coalesced LDG for 32 edges
        const int cnt = min(32, end - base);

        for (int j = 0; j < cnt; j += 8) {
            int   sv[4];
            float xv[4];
            #pragma unroll
            for (int q = 0; q < 4; q++) {
                const int slot = j + 2 * q + half;
                sv[q] = __shfl_sync(0xffffffffu, ce.x, slot);
                xv[q] = __int_as_float(__shfl_sync(0xffffffffu, ce.y, slot));
            }
            float4 zv[4];
            #pragma unroll
            for (int q = 0; q < 4; q++)
                zv[q] = *(const float4*)&g_z[(size_t)sv[q] * OUT_DIM + 4 * lh];
            #pragma unroll
            for (int q = 0; q < 4; q++) {
                denom += xv[q];
                acc.x += xv[q] * zv[q].x;
                acc.y += xv[q] * zv[q].y;
                acc.z += xv[q] * zv[q].z;
                acc.w += xv[q] * zv[q].w;
            }
        }
    }

    acc.x += __shfl_xor_sync(0xffffffffu, acc.x, 16);
    acc.y += __shfl_xor_sync(0xffffffffu, acc.y, 16);
    acc.z += __shfl_xor_sync(0xffffffffu, acc.z, 16);
    acc.w += __shfl_xor_sync(0xffffffffu, acc.w, 16);
    denom += __shfl_xor_sync(0xffffffffu, denom, 16);

    if (half == 0) {
        const float inv = 1.0f / denom;
        float4 o;
        o.x = fmaxf(acc.x * inv + pre.x, 0.f);
        o.y = fmaxf(acc.y * inv + pre.y, 0.f);
        o.z = fmaxf(acc.z * inv + pre.z, 0.f);
        o.w = fmaxf(acc.w * inv + pre.w, 0.f);
        *(float4*)&out[(size_t)node * OUT_DIM + 4 * lh] = o;
    }
}

// ============================================================================
// launch (5 kernels, single stream — R14 shape with kC+count fused)
// ============================================================================
extern "C" void kernel_launch(void* const* d_in, const int* in_sizes, int n_in,
                              void* d_out, int out_size)
{
    const float* h    = (const float*)d_in[0];
    const float* rh   = (const float*)d_in[1];
    const float* W    = (const float*)d_in[2];
    const float* attn = (const float*)d_in[3];
    const float* LW   = (const float*)d_in[4];
    const int*   src  = (const int*)d_in[5];
    const int*   dst  = (const int*)d_in[6];
    float* out = (float*)d_out;

    kCcount<<<KC_BLOCKS + CNT_BLOCKS, 256>>>(W, LW, dst);
    k_gemm<<<K1_BLOCKS, 128>>>(h, W, attn);
    k_scanA<<<N_SBLK, SCAN_BLK>>>();
    k_scanC<<<N_SBLK, SCAN_BLK>>>();
    k2_scatter<<<1184, 256>>>(rh, attn, src, dst);
    k_agg<<<(N_NODES * 32 + 255) / 256, 256>>>(out);
}

// round 17
// speedup vs baseline: 1.0513x; 1.0513x over previous
#include <cuda_runtime.h>

#define N_NODES 50000
#define E_EDGES 800000
#define IN_DIM  128
#define OUT_DIM 64

#define SCAN_BLK 256
#define N_SBLK ((N_NODES + SCAN_BLK - 1) / SCAN_BLK)   // 196
#define K1_BLOCKS 1024
#define CNT_BLOCKS 1024

// ---------------- scratch (device globals; allocation-free) ----------------
__device__ __align__(16) float g_z[N_NODES * OUT_DIM];   // 12.8 MB (L2-resident)
__device__ __align__(16) float g_sl[N_NODES * OUT_DIM];  // self-loop term
__device__ __align__(16) float g_cw[IN_DIM * OUT_DIM];   // C = W^T @ LW  [128][64]
__device__ float g_s1[N_NODES];
__device__ float g_s2[N_NODES];
__device__ int   g_deg[N_NODES];        // zero at call entry (BSS / re-zeroed by scanC)
__device__ int   g_off[N_NODES + 1];    // CSR offsets by dst
__device__ int   g_cur[N_NODES];        // running fill cursor
__device__ int   g_bsum[N_SBLK];        // per-block degree sums
__device__ __align__(8) int2 g_cedge[E_EDGES];  // packed {src, exp_bits} per CSR slot

// ============================================================================
// kC (fast form): one output per thread, 4 independent accumulators.
// 32 blocks x 256 threads = 8192 outputs. ~2us vs 7.5us of the old form.
// ============================================================================
__global__ void __launch_bounds__(256) kC(
    const float* __restrict__ W,    // [64][128]
    const float* __restrict__ LW)   // [64][64]
{
    const int idx = blockIdx.x * 256 + threadIdx.x;   // 0..8191
    const int k = idx >> 6;                           // 0..127
    const int j = idx & 63;                           // 0..63
    float s0 = 0.f, s1 = 0.f, s2 = 0.f, s3 = 0.f;
    #pragma unroll
    for (int o = 0; o < OUT_DIM; o += 4) {
        s0 += W[(o + 0) * IN_DIM + k] * LW[(o + 0) * OUT_DIM + j];
        s1 += W[(o + 1) * IN_DIM + k] * LW[(o + 1) * OUT_DIM + j];
        s2 += W[(o + 2) * IN_DIM + k] * LW[(o + 2) * OUT_DIM + j];
        s3 += W[(o + 3) * IN_DIM + k] * LW[(o + 3) * OUT_DIM + j];
    }
    g_cw[idx] = (s0 + s1) + (s2 + s3);
}

// ============================================================================
// K_fused (exact R14): blocks [0, K1_BLOCKS): z = h@W^T, sl = h@C, s1/s2.
// Blocks [K1_BLOCKS,...): dst degree histogram (hidden under GEMM).
// ============================================================================
__global__ void __launch_bounds__(128) k_fused(
    const float* __restrict__ h,
    const float* __restrict__ W,     // [64][128] row-major
    const float* __restrict__ attn,  // [192] = w1 | w2 | w3
    const int*   __restrict__ dst)
{
    __shared__ __align__(16) float Wts[IN_DIM * 66];      // transposed, padded
    __shared__ __align__(16) float hw[4][IN_DIM][4];      // [warp][k][node-slot]

    const int tid = threadIdx.x;

    if (blockIdx.x >= K1_BLOCKS) {
        const int cbid = blockIdx.x - K1_BLOCKS;
        const int t4 = cbid * 128 + tid;                 // int4 index
        const int n4 = E_EDGES / 4;
        const int stride = CNT_BLOCKS * 128;
        for (int i = t4; i < n4; i += stride) {
            const int4 d = ((const int4*)dst)[i];
            atomicAdd(&g_deg[d.x], 1);
            atomicAdd(&g_deg[d.y], 1);
            atomicAdd(&g_deg[d.z], 1);
            atomicAdd(&g_deg[d.w], 1);
        }
        return;
    }

    for (int i = tid; i < OUT_DIM * IN_DIM; i += blockDim.x) {
        int j = i >> 7;
        int k = i & 127;
        Wts[k * 66 + j] = W[i];
    }
    __syncthreads();

    const int w = tid >> 5;
    const int l = tid & 31;

    const float2 w1 = ((const float2*)attn)[l];
    const float2 w2 = ((const float2*)(attn + OUT_DIM))[l];

    const int ntasks_stride = K1_BLOCKS * 4;
    for (int task = blockIdx.x * 4 + w; task < N_NODES / 4; task += ntasks_stride) {
        const int node0 = task * 4;

        #pragma unroll
        for (int m = 0; m < 4; m++) {
            const float* hp = h + (size_t)(node0 + m) * IN_DIM;
            #pragma unroll
            for (int t = 0; t < 4; t++)
                hw[w][t * 32 + l][m] = hp[t * 32 + l];
        }
        __syncwarp();

        float a0x = 0.f, a0y = 0.f, a0z = 0.f, a0w = 0.f;   // z, out dim 2l
        float a1x = 0.f, a1y = 0.f, a1z = 0.f, a1w = 0.f;   // z, out dim 2l+1
        float b0x = 0.f, b0y = 0.f, b0z = 0.f, b0w = 0.f;   // sl, out dim 2l
        float b1x = 0.f, b1y = 0.f, b1z = 0.f, b1w = 0.f;   // sl, out dim 2l+1
        #pragma unroll 16
        for (int k = 0; k < IN_DIM; k++) {
            const float4 hq = *(const float4*)&hw[w][k][0];
            const float2 wv = *(const float2*)&Wts[k * 66 + 2 * l];
            const float2 cv = __ldg((const float2*)&g_cw[k * OUT_DIM + 2 * l]);
            a0x += wv.x * hq.x; a0y += wv.x * hq.y; a0z += wv.x * hq.z; a0w += wv.x * hq.w;
            a1x += wv.y * hq.x; a1y += wv.y * hq.y; a1z += wv.y * hq.z; a1w += wv.y * hq.w;
            b0x += cv.x * hq.x; b0y += cv.x * hq.y; b0z += cv.x * hq.z; b0w += cv.x * hq.w;
            b1x += cv.y * hq.x; b1y += cv.y * hq.y; b1z += cv.y * hq.z; b1w += cv.y * hq.w;
        }
        __syncwarp();

        const float acc0[4] = {a0x, a0y, a0z, a0w};
        const float acc1[4] = {a1x, a1y, a1z, a1w};
        const float sl0[4]  = {b0x, b0y, b0z, b0w};
        const float sl1[4]  = {b1x, b1y, b1z, b1w};
        #pragma unroll
        for (int m = 0; m < 4; m++) {
            const int node = node0 + m;
            const float zx = acc0[m], zy = acc1[m];
            *(float2*)&g_z[(size_t)node * OUT_DIM + 2 * l]  = make_float2(zx, zy);
            *(float2*)&g_sl[(size_t)node * OUT_DIM + 2 * l] = make_float2(sl0[m], sl1[m]);
            float v1 = zx * w1.x + zy * w1.y;
            float v2 = zx * w2.x + zy * w2.y;
            #pragma unroll
            for (int off = 16; off; off >>= 1) {
                v1 += __shfl_xor_sync(0xffffffffu, v1, off);
                v2 += __shfl_xor_sync(0xffffffffu, v2, off);
            }
            if (l == 0) {
                g_s1[node] = v1;
                g_s2[node] = v2;
            }
        }
    }
}

// ============================================================================
// scanA: per-block degree sums (exact R14)
// ============================================================================
__global__ void __launch_bounds__(SCAN_BLK) k_scanA()
{
    __shared__ int red[SCAN_BLK / 32];
    const int gid = blockIdx.x * SCAN_BLK + threadIdx.x;
    int v = (gid < N_NODES) ? g_deg[gid] : 0;
    #pragma unroll
    for (int off = 16; off; off >>= 1) v += __shfl_xor_sync(0xffffffffu, v, off);
    if ((threadIdx.x & 31) == 0) red[threadIdx.x >> 5] = v;
    __syncthreads();
    if (threadIdx.x == 0) {
        int s = 0;
        #pragma unroll
        for (int i = 0; i < SCAN_BLK / 32; i++) s += red[i];
        g_bsum[blockIdx.x] = s;
    }
}

// ============================================================================
// scanC: block-prefix + local exclusive scan + write off/cur + re-zero deg
// (exact R14)
// ============================================================================
__global__ void __launch_bounds__(SCAN_BLK) k_scanC()
{
    __shared__ int s[SCAN_BLK];
    __shared__ int red[SCAN_BLK / 32];
    __shared__ int s_pre;

    const int t = threadIdx.x;
    const int bid = blockIdx.x;
    const int gid = bid * SCAN_BLK + t;

    int mine = (t < bid) ? g_bsum[t] : 0;     // N_SBLK <= SCAN_BLK
    #pragma unroll
    for (int off = 16; off; off >>= 1) mine += __shfl_xor_sync(0xffffffffu, mine, off);
    if ((t & 31) == 0) red[t >> 5] = mine;
    __syncthreads();
    if (t == 0) {
        int p = 0;
        #pragma unroll
        for (int i = 0; i < SCAN_BLK / 32; i++) p += red[i];
        s_pre = p;
    }

    int v = (gid < N_NODES) ? g_deg[gid] : 0;
    s[t] = v;
    __syncthreads();
    #pragma unroll
    for (int off = 1; off < SCAN_BLK; off <<= 1) {
        int u = (t >= off) ? s[t - off] : 0;
        __syncthreads();
        s[t] += u;
        __syncthreads();
    }

    const int pre = s_pre;
    if (gid < N_NODES) {
        const int o = pre + s[t] - v;   // exclusive
        g_off[gid] = o;
        g_cur[gid] = o;
        g_deg[gid] = 0;                 // ready for next call
        if (gid == N_NODES - 1) g_off[N_NODES] = pre + s[t];
    }
}

// ============================================================================
// K2 (exact R14): logits -> exp -> direct CSR scatter. Half-warp per edge,
// 4 edges in flight. Streaming loads keep g_z resident in L2.
// ============================================================================
__global__ void __launch_bounds__(256) k2_scatter(
    const float* __restrict__ rh,
    const float* __restrict__ attn,
    const int* __restrict__ src,
    const int* __restrict__ dst)
{
    const int tid = blockIdx.x * blockDim.x + threadIdx.x;
    const int hw_id = tid >> 4;
    const int l = tid & 15;
    const int nhw = (gridDim.x * blockDim.x) >> 4;

    const float4 w3 = ((const float4*)(attn + 2 * OUT_DIM))[l];

    for (int e0 = hw_id * 4; e0 < E_EDGES; e0 += nhw * 4) {
        const float4 r0 = __ldcs((const float4*)(rh + (size_t)(e0 + 0) * OUT_DIM) + l);
        const float4 r1 = __ldcs((const float4*)(rh + (size_t)(e0 + 1) * OUT_DIM) + l);
        const float4 r2 = __ldcs((const float4*)(rh + (size_t)(e0 + 2) * OUT_DIM) + l);
        const float4 r3 = __ldcs((const float4*)(rh + (size_t)(e0 + 3) * OUT_DIM) + l);

        float p0 = r0.x * w3.x + r0.y * w3.y + r0.z * w3.z + r0.w * w3.w;
        float p1 = r1.x * w3.x + r1.y * w3.y + r1.z * w3.z + r1.w * w3.w;
        float p2 = r2.x * w3.x + r2.y * w3.y + r2.z * w3.z + r2.w * w3.w;
        float p3 = r3.x * w3.x + r3.y * w3.y + r3.z * w3.z + r3.w * w3.w;
        #pragma unroll
        for (int off = 8; off; off >>= 1) {
            p0 += __shfl_xor_sync(0xffffffffu, p0, off, 16);
            p1 += __shfl_xor_sync(0xffffffffu, p1, off, 16);
            p2 += __shfl_xor_sync(0xffffffffu, p2, off, 16);
            p3 += __shfl_xor_sync(0xffffffffu, p3, off, 16);
        }
        if (l < 4) {
            const int e = e0 + l;
            const float p = (l == 0) ? p0 : (l == 1) ? p1 : (l == 2) ? p2 : p3;
            const int s = src[e];
            const int d = dst[e];
            const float a = g_s1[s] + g_s2[d] + p;
            const float ev = (a > 0.f) ? a : 0.01f * a;   // leaky relu
            const float ex = __expf(ev);                  // no max-sub: |ev| small
            const int pos = atomicAdd(&g_cur[d], 1);
            g_cedge[pos] = make_int2(s, __float_as_int(ex));
        }
    }
}

// ============================================================================
// K_agg (exact R14): warp per node; halves process even/odd edges; lane owns
// 4 dims (float4); ~4 warp-instr/edge; cross-half combine via shfl_xor(16).
// ============================================================================
__global__ void __launch_bounds__(256) k_agg(float* __restrict__ out)
{
    const int node = (blockIdx.x * blockDim.x + threadIdx.x) >> 5;
    const int l = threadIdx.x & 31;
    const int half = l >> 4;     // 0 or 1
    const int lh = l & 15;       // lane within half
    if (node >= N_NODES) return;

    const int beg = g_off[node];
    const int end = g_off[node + 1];

    if (beg == end) {
        if (half == 0)
            *(float4*)&out[(size_t)node * OUT_DIM + 4 * lh] = make_float4(0.f, 0.f, 0.f, 0.f);
        return;
    }

    const float4 pre = *(const float4*)&g_sl[(size_t)node * OUT_DIM + 4 * lh];

    float4 acc = make_float4(0.f, 0.f, 0.f, 0.f);
    float denom = 0.f;

    for (int base = beg; base < end; base += 32) {
        const int idx = base + l;
        int2 ce = make_int2(0, 0);                 // weight bits 0 -> exp=0.0f
        if (idx < end) ce = g_cedge[idx];          // ONE coalesced LDG for 32 edges
        const int cnt = min(32, end - base);

        for (int j = 0; j < cnt; j += 8) {
            int   sv[4];
            float xv[4];
            #pragma unroll
            for (int q = 0; q < 4; q++) {
                const int slot = j + 2 * q + half;
                sv[q] = __shfl_sync(0xffffffffu, ce.x, slot);
                xv[q] = __int_as_float(__shfl_sync(0xffffffffu, ce.y, slot));
            }
            float4 zv[4];
            #pragma unroll
            for (int q = 0; q < 4; q++)
                zv[q] = *(const float4*)&g_z[(size_t)sv[q] * OUT_DIM + 4 * lh];
            #pragma unroll
            for (int q = 0; q < 4; q++) {
                denom += xv[q];
                acc.x += xv[q] * zv[q].x;
                acc.y += xv[q] * zv[q].y;
                acc.z += xv[q] * zv[q].z;
                acc.w += xv[q] * zv[q].w;
            }
        }
    }

    acc.x += __shfl_xor_sync(0xffffffffu, acc.x, 16);
    acc.y += __shfl_xor_sync(0xffffffffu, acc.y, 16);
    acc.z += __shfl_xor_sync(0xffffffffu, acc.z, 16);
    acc.w += __shfl_xor_sync(0xffffffffu, acc.w, 16);
    denom += __shfl_xor_sync(0xffffffffu, denom, 16);

    if (half == 0) {
        const float inv = 1.0f / denom;
        float4 o;
        o.x = fmaxf(acc.x * inv + pre.x, 0.f);
        o.y = fmaxf(acc.y * inv + pre.y, 0.f);
        o.z = fmaxf(acc.z * inv + pre.z, 0.f);
        o.w = fmaxf(acc.w * inv + pre.w, 0.f);
        *(float4*)&out[(size_t)node * OUT_DIM + 4 * lh] = o;
    }
}

// ============================================================================
// launch (6 kernels, exact R14 shape; only kC internals improved)
// ============================================================================
extern "C" void kernel_launch(void* const* d_in, const int* in_sizes, int n_in,
                              void* d_out, int out_size)
{
    const float* h    = (const float*)d_in[0];
    const float* rh   = (const float*)d_in[1];
    const float* W    = (const float*)d_in[2];
    const float* attn = (const float*)d_in[3];
    const float* LW   = (const float*)d_in[4];
    const int*   src  = (const int*)d_in[5];
    const int*   dst  = (const int*)d_in[6];
    float* out = (float*)d_out;

    kC<<<32, 256>>>(W, LW);
    k_fused<<<K1_BLOCKS + CNT_BLOCKS, 128>>>(h, W, attn, dst);
    k_scanA<<<N_SBLK, SCAN_BLK>>>();
    k_scanC<<<N_SBLK, SCAN_BLK>>>();
    k2_scatter<<<1184, 256>>>(rh, attn, src, dst);
    k_agg<<<(N_NODES * 32 + 255) / 256, 256>>>(out);
}